// round 5
// baseline (speedup 1.0000x reference)
#include <cuda_runtime.h>
#include <cstdint>

#define N_NODES 50000
#define N_EDGES 800000
#define IN_CH   256
#define OUT_CH  64
#define HEADS   4
#define OUTF    (HEADS * OUT_CH)   // 256

// ---------------- device scratch (no allocs allowed) ----------------
__device__ __align__(16) float    g_xh[(size_t)N_NODES * OUTF];     // projected features [N, 256]
__device__ __align__(16) float    g_asrc[N_NODES * HEADS];          // [N, 4]
__device__ __align__(16) float    g_adst[N_NODES * HEADS];          // [N, 4]
__device__ __align__(16) unsigned g_amax[N_NODES * HEADS];          // encoded float max
__device__ __align__(16) float    g_asum[N_NODES * HEADS];          // softmax denominators
__device__ __align__(16) float    g_ae[(size_t)N_EDGES * HEADS];    // per-edge logits -> exps

// clamp to valid node range (branch-free; hardening against dtype surprises)
__device__ __forceinline__ int clamp_idx(int v) {
    return min(max(v, 0), N_NODES - 1);
}

// order-preserving float<->uint map for atomicMax on signed floats
__device__ __forceinline__ unsigned enc_f(float f) {
    unsigned u = __float_as_uint(f);
    return (u & 0x80000000u) ? ~u : (u | 0x80000000u);
}
__device__ __forceinline__ float dec_f(unsigned u) {
    return (u & 0x80000000u) ? __uint_as_float(u & 0x7fffffffu)
                             : __uint_as_float(~u);
}

__device__ __forceinline__ void red_add_v4(float4* addr, float4 v) {
    asm volatile("red.global.add.v4.f32 [%0], {%1, %2, %3, %4};"
                 :: "l"(addr), "f"(v.x), "f"(v.y), "f"(v.z), "f"(v.w)
                 : "memory");
}

// ---------------- init: out <- bias, amax <- floor, asum <- 0 ----------------
__global__ void k_init(const float* __restrict__ bias, float* __restrict__ out) {
    int i = blockIdx.x * blockDim.x + threadIdx.x;
    if (i < N_NODES * OUTF) out[i] = bias[i & (OUTF - 1)];
    if (i < N_NODES * HEADS) { g_amax[i] = 0u; g_asum[i] = 0.f; }
}

// ---------------- projection GEMM: x [N,256] @ W[h] [256,64] -> g_xh ----------------
// block = (128 rows) x (1 head of 64 cols), 256 threads, 8x4 microtile, BK=16
__global__ void k_gemm(const float* __restrict__ x, const float* __restrict__ w) {
    constexpr int BM = 128, BN = 64, BK = 16, TM = 8, TN = 4;
    __shared__ float As[BK][BM];     // 8 KB
    __shared__ float Bs[BK][BN];     // 4 KB

    const int tid = threadIdx.x;
    const int m0  = blockIdx.x * BM;
    const int h   = blockIdx.y;
    const float* wh = w + (size_t)h * IN_CH * OUT_CH;   // [256][64]

    const int tx = tid & 15;   // N dir (16 * TN = 64)
    const int ty = tid >> 4;   // M dir (16 * TM = 128)

    float acc[TM][TN];
    #pragma unroll
    for (int i = 0; i < TM; i++)
        #pragma unroll
        for (int j = 0; j < TN; j++) acc[i][j] = 0.f;

    for (int k0 = 0; k0 < IN_CH; k0 += BK) {
        // load A tile: 128x16 = 512 float4, 2 per thread, transposed store
        #pragma unroll
        for (int t = 0; t < 2; t++) {
            int idx = tid + t * 256;        // 0..511
            int ar  = idx >> 2;             // 0..127
            int ac  = (idx & 3) * 4;        // 0,4,8,12
            float4 v = make_float4(0.f, 0.f, 0.f, 0.f);
            if (m0 + ar < N_NODES)
                v = *reinterpret_cast<const float4*>(x + (size_t)(m0 + ar) * IN_CH + k0 + ac);
            As[ac + 0][ar] = v.x;
            As[ac + 1][ar] = v.y;
            As[ac + 2][ar] = v.z;
            As[ac + 3][ar] = v.w;
        }
        // load B tile: 16x64 = 256 float4, 1 per thread
        {
            int br = tid >> 4;          // k row 0..15
            int bc = (tid & 15) * 4;    // 0..60
            float4 v = *reinterpret_cast<const float4*>(wh + (size_t)(k0 + br) * OUT_CH + bc);
            *reinterpret_cast<float4*>(&Bs[br][bc]) = v;
        }
        __syncthreads();

        #pragma unroll
        for (int k = 0; k < BK; k++) {
            float a[TM], b[TN];
            #pragma unroll
            for (int i = 0; i < TM; i++) a[i] = As[k][ty * TM + i];
            #pragma unroll
            for (int j = 0; j < TN; j++) b[j] = Bs[k][tx * TN + j];
            #pragma unroll
            for (int i = 0; i < TM; i++)
                #pragma unroll
                for (int j = 0; j < TN; j++) acc[i][j] = fmaf(a[i], b[j], acc[i][j]);
        }
        __syncthreads();
    }

    // write: g_xh[m][h*64 + tx*4 + j]
    #pragma unroll
    for (int i = 0; i < TM; i++) {
        int m = m0 + ty * TM + i;
        if (m < N_NODES) {
            float4 v = make_float4(acc[i][0], acc[i][1], acc[i][2], acc[i][3]);
            *reinterpret_cast<float4*>(g_xh + (size_t)m * OUTF + h * OUT_CH + tx * TN) = v;
        }
    }
}

// ---------------- attention logits per (node, head) ----------------
__global__ void k_alpha(const float* __restrict__ att_src, const float* __restrict__ att_dst) {
    int i = blockIdx.x * blockDim.x + threadIdx.x;
    if (i >= N_NODES * HEADS) return;
    int n = i >> 2, h = i & 3;
    const float4* xr = reinterpret_cast<const float4*>(g_xh) + (size_t)n * 64 + h * 16;
    const float4* sa = reinterpret_cast<const float4*>(att_src) + h * 16;
    const float4* da = reinterpret_cast<const float4*>(att_dst) + h * 16;
    float s = 0.f, d = 0.f;
    #pragma unroll
    for (int t = 0; t < 16; t++) {
        float4 v = xr[t];
        float4 a = sa[t];
        float4 b = da[t];
        s += v.x * a.x + v.y * a.y + v.z * a.z + v.w * a.w;
        d += v.x * b.x + v.y * b.y + v.z * b.z + v.w * b.w;
    }
    g_asrc[i] = s;
    g_adst[i] = d;
}

// ---------------- edge pass 1: logits + segment max (edge_index is INT32) ----------------
__global__ void k_edge_max(const int* __restrict__ ei) {
    int e = blockIdx.x * blockDim.x + threadIdx.x;
    if (e >= N_EDGES) return;
    int row = clamp_idx(ei[e]);
    int col = clamp_idx(ei[N_EDGES + e]);
    float4 s = *reinterpret_cast<const float4*>(g_asrc + row * 4);
    float4 d = *reinterpret_cast<const float4*>(g_adst + col * 4);
    float a0 = s.x + d.x, a1 = s.y + d.y, a2 = s.z + d.z, a3 = s.w + d.w;
    a0 = a0 > 0.f ? a0 : 0.2f * a0;
    a1 = a1 > 0.f ? a1 : 0.2f * a1;
    a2 = a2 > 0.f ? a2 : 0.2f * a2;
    a3 = a3 > 0.f ? a3 : 0.2f * a3;
    *reinterpret_cast<float4*>(g_ae + (size_t)e * 4) = make_float4(a0, a1, a2, a3);
    atomicMax(&g_amax[row * 4 + 0], enc_f(a0));
    atomicMax(&g_amax[row * 4 + 1], enc_f(a1));
    atomicMax(&g_amax[row * 4 + 2], enc_f(a2));
    atomicMax(&g_amax[row * 4 + 3], enc_f(a3));
}

// ---------------- edge pass 2: exp + segment sum (exps cached in g_ae) ----------------
__global__ void k_edge_exp(const int* __restrict__ ei) {
    int e = blockIdx.x * blockDim.x + threadIdx.x;
    if (e >= N_EDGES) return;
    int row = clamp_idx(ei[e]);
    float4 a = *reinterpret_cast<const float4*>(g_ae + (size_t)e * 4);
    uint4  mu = *reinterpret_cast<const uint4*>(g_amax + row * 4);
    float p0 = __expf(a.x - dec_f(mu.x));
    float p1 = __expf(a.y - dec_f(mu.y));
    float p2 = __expf(a.z - dec_f(mu.z));
    float p3 = __expf(a.w - dec_f(mu.w));
    *reinterpret_cast<float4*>(g_ae + (size_t)e * 4) = make_float4(p0, p1, p2, p3);
    atomicAdd(&g_asum[row * 4 + 0], p0);
    atomicAdd(&g_asum[row * 4 + 1], p1);
    atomicAdd(&g_asum[row * 4 + 2], p2);
    atomicAdd(&g_asum[row * 4 + 3], p3);
}

// ---------------- edge pass 3: scatter messages (warp per edge, red.v4) ----------------
__global__ void k_scatter(const int* __restrict__ ei, float* __restrict__ out) {
    int e = blockIdx.x * (blockDim.x >> 5) + (threadIdx.x >> 5);
    if (e >= N_EDGES) return;
    int lane = threadIdx.x & 31;
    int row = clamp_idx(ei[e]);
    int col = clamp_idx(ei[N_EDGES + e]);

    float4 p  = *reinterpret_cast<const float4*>(g_ae + (size_t)e * 4);
    float4 sm = *reinterpret_cast<const float4*>(g_asum + row * 4);
    float alpha[4];
    alpha[0] = p.x / fmaxf(sm.x, 1e-16f);
    alpha[1] = p.y / fmaxf(sm.y, 1e-16f);
    alpha[2] = p.z / fmaxf(sm.z, 1e-16f);
    alpha[3] = p.w / fmaxf(sm.w, 1e-16f);

    const float4* src = reinterpret_cast<const float4*>(g_xh) + (size_t)col * 64;
    float4*       dst = reinterpret_cast<float4*>(out) + (size_t)row * 64;

    #pragma unroll
    for (int t = 0; t < 2; t++) {
        int j = lane + t * 32;           // float4 index 0..63; head = j/16
        float a = alpha[j >> 4];
        float4 v = src[j];
        v.x *= a; v.y *= a; v.z *= a; v.w *= a;
        red_add_v4(dst + j, v);
    }
}

// ---------------- launch ----------------
extern "C" void kernel_launch(void* const* d_in, const int* in_sizes, int n_in,
                              void* d_out, int out_size) {
    const float* x       = (const float*)d_in[0];
    const int*   ei      = (const int*)d_in[1];       // int32! (JAX x64 disabled)
    const float* w       = (const float*)d_in[2];
    const float* att_src = (const float*)d_in[3];
    const float* att_dst = (const float*)d_in[4];
    const float* bias    = (const float*)d_in[5];
    float*       out     = (float*)d_out;

    k_init<<<(N_NODES * OUTF + 255) / 256, 256>>>(bias, out);

    dim3 gg((N_NODES + 127) / 128, HEADS);
    k_gemm<<<gg, 256>>>(x, w);

    k_alpha<<<(N_NODES * HEADS + 255) / 256, 256>>>(att_src, att_dst);
    k_edge_max<<<(N_EDGES + 255) / 256, 256>>>(ei);
    k_edge_exp<<<(N_EDGES + 255) / 256, 256>>>(ei);
    k_scatter<<<(N_EDGES + 7) / 8, 256>>>(ei, out);
}

// round 7
// speedup vs baseline: 1.2197x; 1.2197x over previous
#include <cuda_runtime.h>
#include <cstdint>

#define N_NODES 50000
#define N_EDGES 800000
#define IN_CH   256
#define OUT_CH  64
#define HEADS   4
#define OUTF    (HEADS * OUT_CH)   // 256

// ---------------- device scratch (no allocs allowed) ----------------
__device__ __align__(16) float g_xh[(size_t)N_NODES * OUTF];    // projected features [N, 256]
__device__ __align__(16) float g_asrc[N_NODES * HEADS];         // [N, 4]
__device__ __align__(16) float g_adst[N_NODES * HEADS];         // [N, 4]
__device__ int g_cnt[N_NODES];                                  // per-row edge count
__device__ int g_off[N_NODES + 1];                              // CSR offsets
__device__ int g_cur[N_NODES];                                  // reorder cursors
__device__ int g_ecol[N_EDGES];                                 // CSR col per slot
__device__ __align__(16) float g_eexp[(size_t)N_EDGES * HEADS]; // CSR exp(logit) per slot

__device__ __forceinline__ int clamp_idx(int v) {
    return min(max(v, 0), N_NODES - 1);
}

// ---------------- init: zero row histogram ----------------
__global__ void k_init() {
    int i = blockIdx.x * blockDim.x + threadIdx.x;
    if (i < N_NODES) g_cnt[i] = 0;
}

// ---------------- projection GEMM: x [N,256] @ W[h] [256,64] -> g_xh ----------------
__global__ void k_gemm(const float* __restrict__ x, const float* __restrict__ w) {
    constexpr int BM = 128, BN = 64, BK = 16, TM = 8, TN = 4;
    __shared__ float As[BK][BM];
    __shared__ float Bs[BK][BN];

    const int tid = threadIdx.x;
    const int m0  = blockIdx.x * BM;
    const int h   = blockIdx.y;
    const float* wh = w + (size_t)h * IN_CH * OUT_CH;

    const int tx = tid & 15;
    const int ty = tid >> 4;

    float acc[TM][TN];
    #pragma unroll
    for (int i = 0; i < TM; i++)
        #pragma unroll
        for (int j = 0; j < TN; j++) acc[i][j] = 0.f;

    for (int k0 = 0; k0 < IN_CH; k0 += BK) {
        #pragma unroll
        for (int t = 0; t < 2; t++) {
            int idx = tid + t * 256;
            int ar  = idx >> 2;
            int ac  = (idx & 3) * 4;
            float4 v = make_float4(0.f, 0.f, 0.f, 0.f);
            if (m0 + ar < N_NODES)
                v = *reinterpret_cast<const float4*>(x + (size_t)(m0 + ar) * IN_CH + k0 + ac);
            As[ac + 0][ar] = v.x;
            As[ac + 1][ar] = v.y;
            As[ac + 2][ar] = v.z;
            As[ac + 3][ar] = v.w;
        }
        {
            int br = tid >> 4;
            int bc = (tid & 15) * 4;
            float4 v = *reinterpret_cast<const float4*>(wh + (size_t)(k0 + br) * OUT_CH + bc);
            *reinterpret_cast<float4*>(&Bs[br][bc]) = v;
        }
        __syncthreads();

        #pragma unroll
        for (int k = 0; k < BK; k++) {
            float a[TM], b[TN];
            #pragma unroll
            for (int i = 0; i < TM; i++) a[i] = As[k][ty * TM + i];
            #pragma unroll
            for (int j = 0; j < TN; j++) b[j] = Bs[k][tx * TN + j];
            #pragma unroll
            for (int i = 0; i < TM; i++)
                #pragma unroll
                for (int j = 0; j < TN; j++) acc[i][j] = fmaf(a[i], b[j], acc[i][j]);
        }
        __syncthreads();
    }

    #pragma unroll
    for (int i = 0; i < TM; i++) {
        int m = m0 + ty * TM + i;
        if (m < N_NODES) {
            float4 v = make_float4(acc[i][0], acc[i][1], acc[i][2], acc[i][3]);
            *reinterpret_cast<float4*>(g_xh + (size_t)m * OUTF + h * OUT_CH + tx * TN) = v;
        }
    }
}

// ---------------- attention logits per (node, head) ----------------
__global__ void k_alpha(const float* __restrict__ att_src, const float* __restrict__ att_dst) {
    int i = blockIdx.x * blockDim.x + threadIdx.x;
    if (i >= N_NODES * HEADS) return;
    int n = i >> 2, h = i & 3;
    const float4* xr = reinterpret_cast<const float4*>(g_xh) + (size_t)n * 64 + h * 16;
    const float4* sa = reinterpret_cast<const float4*>(att_src) + h * 16;
    const float4* da = reinterpret_cast<const float4*>(att_dst) + h * 16;
    float s = 0.f, d = 0.f;
    #pragma unroll
    for (int t = 0; t < 16; t++) {
        float4 v = xr[t];
        float4 a = sa[t];
        float4 b = da[t];
        s += v.x * a.x + v.y * a.y + v.z * a.z + v.w * a.w;
        d += v.x * b.x + v.y * b.y + v.z * b.z + v.w * b.w;
    }
    g_asrc[i] = s;
    g_adst[i] = d;
}

// ---------------- histogram of destination rows ----------------
__global__ void k_hist(const int* __restrict__ ei) {
    int e = blockIdx.x * blockDim.x + threadIdx.x;
    if (e >= N_EDGES) return;
    atomicAdd(&g_cnt[clamp_idx(ei[e])], 1);
}

// ---------------- exclusive scan over 50k counters (single block) ----------------
__global__ void k_scan() {
    constexpr int T = 1024;
    constexpr int CHUNK = (N_NODES + T - 1) / T;   // 49
    __shared__ int partial[T];
    int t = threadIdx.x;
    int beg = t * CHUNK;
    int end = min(beg + CHUNK, N_NODES);
    int s = 0;
    for (int i = beg; i < end; i++) s += g_cnt[i];
    partial[t] = s;
    __syncthreads();
    // Hillis-Steele inclusive scan
    for (int d = 1; d < T; d <<= 1) {
        int v = partial[t];
        int add = (t >= d) ? partial[t - d] : 0;
        __syncthreads();
        partial[t] = v + add;
        __syncthreads();
    }
    int run = (t > 0) ? partial[t - 1] : 0;
    for (int i = beg; i < end; i++) {
        g_off[i] = run;
        g_cur[i] = run;
        run += g_cnt[i];
    }
    if (t == T - 1) g_off[N_NODES] = N_EDGES;
}

// ---------------- fused edge pass: logits -> exp, reorder into CSR slots ----------------
// (no max subtraction: exp(a)/sum exp(a) == softmax exactly; |logit| small here)
__global__ void k_edge_fused(const int* __restrict__ ei) {
    int e = blockIdx.x * blockDim.x + threadIdx.x;
    if (e >= N_EDGES) return;
    int row = clamp_idx(ei[e]);
    int col = clamp_idx(ei[N_EDGES + e]);
    float4 s = *reinterpret_cast<const float4*>(g_asrc + row * 4);
    float4 d = *reinterpret_cast<const float4*>(g_adst + col * 4);
    float a0 = s.x + d.x, a1 = s.y + d.y, a2 = s.z + d.z, a3 = s.w + d.w;
    a0 = a0 > 0.f ? a0 : 0.2f * a0;
    a1 = a1 > 0.f ? a1 : 0.2f * a1;
    a2 = a2 > 0.f ? a2 : 0.2f * a2;
    a3 = a3 > 0.f ? a3 : 0.2f * a3;
    float4 p = make_float4(__expf(a0), __expf(a1), __expf(a2), __expf(a3));
    int pos = atomicAdd(&g_cur[row], 1);
    g_ecol[pos] = col;
    *reinterpret_cast<float4*>(g_eexp + (size_t)pos * 4) = p;
}

// ---------------- CSR gather: one warp per destination node, no atomics ----------------
__global__ void k_csr(const float* __restrict__ bias, float* __restrict__ out) {
    int warp = (blockIdx.x * blockDim.x + threadIdx.x) >> 5;
    if (warp >= N_NODES) return;
    int lane = threadIdx.x & 31;
    int n = warp;
    int off = g_off[n];
    int deg = g_off[n + 1] - off;

    // pass 1: sum of exps per head (lanes stride over edges, then warp-reduce)
    float4 sum = make_float4(0.f, 0.f, 0.f, 0.f);
    for (int i = off + lane; i < off + deg; i += 32) {
        float4 p = *reinterpret_cast<const float4*>(g_eexp + (size_t)i * 4);
        sum.x += p.x; sum.y += p.y; sum.z += p.z; sum.w += p.w;
    }
    #pragma unroll
    for (int d = 16; d > 0; d >>= 1) {
        sum.x += __shfl_xor_sync(0xffffffffu, sum.x, d);
        sum.y += __shfl_xor_sync(0xffffffffu, sum.y, d);
        sum.z += __shfl_xor_sync(0xffffffffu, sum.z, d);
        sum.w += __shfl_xor_sync(0xffffffffu, sum.w, d);
    }
    float4 r;
    r.x = 1.f / fmaxf(sum.x, 1e-16f);
    r.y = 1.f / fmaxf(sum.y, 1e-16f);
    r.z = 1.f / fmaxf(sum.z, 1e-16f);
    r.w = 1.f / fmaxf(sum.w, 1e-16f);

    // pass 2: accumulate alpha-weighted source rows.
    // lane owns float4 slots lane and lane+32 of the 64-slot (256-float) output row.
    const int j0 = lane, j1 = lane + 32;
    const int h0 = j0 >> 4;        // 0 or 1
    const int h1 = j1 >> 4;        // 2 or 3
    float4 acc0 = make_float4(0.f, 0.f, 0.f, 0.f);
    float4 acc1 = make_float4(0.f, 0.f, 0.f, 0.f);

    for (int j = 0; j < deg; j++) {
        int idx = off + j;
        int c = g_ecol[idx];                                              // broadcast
        float4 p = *reinterpret_cast<const float4*>(g_eexp + (size_t)idx * 4); // broadcast
        float a0 = h0 ? (p.y * r.y) : (p.x * r.x);
        float a1 = (h1 == 3) ? (p.w * r.w) : (p.z * r.z);
        const float4* src = reinterpret_cast<const float4*>(g_xh) + (size_t)c * 64;
        float4 v = src[j0];
        float4 u = src[j1];
        acc0.x = fmaf(a0, v.x, acc0.x); acc0.y = fmaf(a0, v.y, acc0.y);
        acc0.z = fmaf(a0, v.z, acc0.z); acc0.w = fmaf(a0, v.w, acc0.w);
        acc1.x = fmaf(a1, u.x, acc1.x); acc1.y = fmaf(a1, u.y, acc1.y);
        acc1.z = fmaf(a1, u.z, acc1.z); acc1.w = fmaf(a1, u.w, acc1.w);
    }

    const float4* b4 = reinterpret_cast<const float4*>(bias);
    float4 b0 = b4[j0], b1 = b4[j1];
    acc0.x += b0.x; acc0.y += b0.y; acc0.z += b0.z; acc0.w += b0.w;
    acc1.x += b1.x; acc1.y += b1.y; acc1.z += b1.z; acc1.w += b1.w;
    float4* dst = reinterpret_cast<float4*>(out) + (size_t)n * 64;
    dst[j0] = acc0;
    dst[j1] = acc1;
}

// ---------------- launch ----------------
extern "C" void kernel_launch(void* const* d_in, const int* in_sizes, int n_in,
                              void* d_out, int out_size) {
    const float* x       = (const float*)d_in[0];
    const int*   ei      = (const int*)d_in[1];       // int32 (JAX x64 disabled)
    const float* w       = (const float*)d_in[2];
    const float* att_src = (const float*)d_in[3];
    const float* att_dst = (const float*)d_in[4];
    const float* bias    = (const float*)d_in[5];
    float*       out     = (float*)d_out;

    k_init<<<(N_NODES + 255) / 256, 256>>>();
    k_hist<<<(N_EDGES + 255) / 256, 256>>>(ei);
    k_scan<<<1, 1024>>>();

    dim3 gg((N_NODES + 127) / 128, HEADS);
    k_gemm<<<gg, 256>>>(x, w);

    k_alpha<<<(N_NODES * HEADS + 255) / 256, 256>>>(att_src, att_dst);
    k_edge_fused<<<(N_EDGES + 255) / 256, 256>>>(ei);
    k_csr<<<(N_NODES * 32 + 255) / 256, 256>>>(bias, out);
}